// round 4
// baseline (speedup 1.0000x reference)
#include <cuda_runtime.h>
#include <cuda_fp16.h>
#include <mma.h>

using namespace nvcuda;

#define HIDDEN   2048
#define NHEADS   32
#define HDIM     64
#define SEQ      4096
#define NTOK     32768           // B * S = 8 * 4096

// ---------------- scratch (static device globals; no allocation) ----------------
__device__ __half g_x[(size_t)NTOK * HIDDEN];          // LN output, fp16      (128 MB)
__device__ __half g_w[4][(size_t)HIDDEN * HIDDEN];     // wq,wk,wv,wo fp16     ( 33 MB)
__device__ __half g_qkv[(size_t)NTOK * 3 * HIDDEN];    // q|k|v per token      (402 MB)
__device__ __half g_attn[(size_t)NTOK * HIDDEN];       // attention output     (128 MB)

// ---------------- LayerNorm -> fp16 ----------------
__device__ __forceinline__ float warp_red(float v) {
    #pragma unroll
    for (int o = 16; o; o >>= 1) v += __shfl_xor_sync(0xffffffffu, v, o);
    return v;
}

__global__ __launch_bounds__(256) void ln_kernel(const float* __restrict__ hs,
                          const float* __restrict__ gamma,
                          const float* __restrict__ beta) {
    int t = blockIdx.x;
    int tid = threadIdx.x;                     // 256 threads
    const float4* row = (const float4*)(hs + (size_t)t * HIDDEN);
    float4 v0 = row[tid];
    float4 v1 = row[tid + 256];
    float s = v0.x + v0.y + v0.z + v0.w + v1.x + v1.y + v1.z + v1.w;
    float q = v0.x*v0.x + v0.y*v0.y + v0.z*v0.z + v0.w*v0.w
            + v1.x*v1.x + v1.y*v1.y + v1.z*v1.z + v1.w*v1.w;
    s = warp_red(s);
    q = warp_red(q);
    __shared__ float sh_s[8], sh_q[8];
    int w = tid >> 5, l = tid & 31;
    if (l == 0) { sh_s[w] = s; sh_q[w] = q; }
    __syncthreads();
    float st = 0.f, qt = 0.f;
    #pragma unroll
    for (int i = 0; i < 8; i++) { st += sh_s[i]; qt += sh_q[i]; }
    float mean = st * (1.0f / HIDDEN);
    float var  = qt * (1.0f / HIDDEN) - mean * mean;
    float rstd = rsqrtf(var + 1e-5f);

    const float4* g4 = (const float4*)gamma;
    const float4* b4 = (const float4*)beta;
    __half2* out = (__half2*)(g_x + (size_t)t * HIDDEN);

    {
        float4 g = g4[tid], b = b4[tid];
        float y0 = (v0.x - mean) * rstd * g.x + b.x;
        float y1 = (v0.y - mean) * rstd * g.y + b.y;
        float y2 = (v0.z - mean) * rstd * g.z + b.z;
        float y3 = (v0.w - mean) * rstd * g.w + b.w;
        out[2*tid]   = __floats2half2_rn(y0, y1);
        out[2*tid+1] = __floats2half2_rn(y2, y3);
    }
    {
        int i2 = tid + 256;
        float4 g = g4[i2], b = b4[i2];
        float y0 = (v1.x - mean) * rstd * g.x + b.x;
        float y1 = (v1.y - mean) * rstd * g.y + b.y;
        float y2 = (v1.z - mean) * rstd * g.z + b.z;
        float y3 = (v1.w - mean) * rstd * g.w + b.w;
        out[2*i2]   = __floats2half2_rn(y0, y1);
        out[2*i2+1] = __floats2half2_rn(y2, y3);
    }
}

// ---------------- weight fp32 -> fp16 ----------------
__global__ __launch_bounds__(256) void cvt_kernel(const float* __restrict__ w, __half* __restrict__ o) {
    int i = blockIdx.x * blockDim.x + threadIdx.x;   // over float4 groups
    float4 f = ((const float4*)w)[i];
    ((__half2*)o)[2*i]   = __floats2half2_rn(f.x, f.y);
    ((__half2*)o)[2*i+1] = __floats2half2_rn(f.z, f.w);
}

// ---------------- tiled wmma GEMM: C[M,N] = A[M,2048] * B[2048,N] ----------------
// BM=128, BN=128, BK=64, 256 threads (8 warps: 4 along M x 2 along N, warp tile 32x64)
#define BMT 128
#define BNT 128
#define BKT 64
#define LDA_S 72     // As: [128][72] half
#define LDB_S 136    // Bs: [64][136] half

template<bool QKV>
__global__ __launch_bounds__(256) void gemm_kernel(const __half* __restrict__ A, void* __restrict__ Cout) {
    extern __shared__ char smem[];
    __half* As = (__half*)smem;                                   // 128*72*2  = 18432 B
    __half* Bs = (__half*)(smem + BMT * LDA_S * sizeof(__half));  // 64*136*2  = 17408 B
    float*  Cs = (float*)smem;                                    // epilogue: 128*64*4 = 32768 B (reuse)

    int tid  = threadIdx.x;
    int warp = tid >> 5;
    int wm = (warp & 3) * 32;          // warp M offset inside tile
    int wg = warp >> 2;                // warp N group (0 or 1)
    int wn = wg * 64;
    int m0  = blockIdx.y * BMT;
    int n0g = blockIdx.x * BNT;

    const __half* Bw;
    int bn0;
    if (QKV) { Bw = g_w[0] + ((size_t)(n0g >> 11) << 22); bn0 = n0g & 2047; }
    else     { Bw = g_w[3];                               bn0 = n0g;        }

    wmma::fragment<wmma::accumulator, 16, 16, 16, float> acc[2][4];
    #pragma unroll
    for (int mi = 0; mi < 2; mi++)
        #pragma unroll
        for (int ni = 0; ni < 4; ni++)
            wmma::fill_fragment(acc[mi][ni], 0.0f);

    for (int kt = 0; kt < HIDDEN; kt += BKT) {
        // load A tile: 128x64 halfs = 1024 int4
        #pragma unroll
        for (int r = 0; r < 4; r++) {
            int v = tid + r * 256;
            int row = v >> 3, c8 = v & 7;
            *(int4*)(As + row * LDA_S + c8 * 8) =
                *(const int4*)(A + (size_t)(m0 + row) * HIDDEN + kt + c8 * 8);
        }
        // load B tile: 64x128 halfs = 1024 int4
        #pragma unroll
        for (int r = 0; r < 4; r++) {
            int v = tid + r * 256;
            int row = v >> 4, c8 = v & 15;
            *(int4*)(Bs + row * LDB_S + c8 * 8) =
                *(const int4*)(Bw + (size_t)(kt + row) * HIDDEN + bn0 + c8 * 8);
        }
        __syncthreads();

        #pragma unroll
        for (int kk = 0; kk < BKT; kk += 16) {
            wmma::fragment<wmma::matrix_a, 16, 16, 16, __half, wmma::row_major> af[2];
            wmma::fragment<wmma::matrix_b, 16, 16, 16, __half, wmma::row_major> bf[4];
            #pragma unroll
            for (int mi = 0; mi < 2; mi++)
                wmma::load_matrix_sync(af[mi], As + (wm + mi * 16) * LDA_S + kk, LDA_S);
            #pragma unroll
            for (int ni = 0; ni < 4; ni++)
                wmma::load_matrix_sync(bf[ni], Bs + kk * LDB_S + wn + ni * 16, LDB_S);
            #pragma unroll
            for (int mi = 0; mi < 2; mi++)
                #pragma unroll
                for (int ni = 0; ni < 4; ni++)
                    wmma::mma_sync(acc[mi][ni], af[mi], bf[ni], acc[mi][ni]);
        }
        __syncthreads();
    }

    // epilogue in 2 phases (cols 0-63 from warp group 0, then 64-127 from group 1)
    #pragma unroll
    for (int ph = 0; ph < 2; ph++) {
        if (wg == ph) {
            #pragma unroll
            for (int mi = 0; mi < 2; mi++)
                #pragma unroll
                for (int ni = 0; ni < 4; ni++)
                    wmma::store_matrix_sync(Cs + (wm + mi * 16) * 64 + ni * 16,
                                            acc[mi][ni], 64, wmma::mem_row_major);
        }
        __syncthreads();
        {
            int row  = tid >> 1;
            int cseg = (tid & 1) * 32;
            int gcol = n0g + ph * 64 + cseg;
            const float* src = Cs + row * 64 + cseg;
            if (QKV) {
                __half* dst = ((__half*)Cout) + (size_t)(m0 + row) * (3 * HIDDEN) + gcol;
                #pragma unroll
                for (int c = 0; c < 32; c += 2)
                    *(__half2*)(dst + c) = __floats2half2_rn(src[c], src[c + 1]);
            } else {
                float* dst = ((float*)Cout) + (size_t)(m0 + row) * HIDDEN + gcol;
                #pragma unroll
                for (int c = 0; c < 32; c += 4)
                    *(float4*)(dst + c) = *(const float4*)(src + c);
            }
        }
        __syncthreads();
    }
}

// ---------------- per-token RoPE + 32x32 head-attention ----------------
__global__ __launch_bounds__(128) void attn_kernel() {
    int t = blockIdx.x;
    int s = t & (SEQ - 1);
    int tid = threadIdx.x;                 // 128 threads

    __shared__ float qs[32][68], ks[32][68], vs[32][68];
    __shared__ float ss[32][33];
    __shared__ float cosv[32], sinv[32];

    if (tid < 32) {
        float e = (float)(2 * tid) / 64.0f;
        float p = powf(10000.0f, e);
        float ang = (float)s * (1.0f / p);
        sinv[tid] = sinf(ang);
        cosv[tid] = cosf(ang);
    }
    __syncthreads();

    const __half* qg = g_qkv + (size_t)t * (3 * HIDDEN);
    const __half* kg = qg + HIDDEN;
    const __half* vg = qg + 2 * HIDDEN;

    // RoPE (note: angle depends on HEAD index only; rotate_half mixes even/odd dims)
    #pragma unroll
    for (int idx = tid; idx < HIDDEN; idx += 128) {
        int h = idx >> 6, d = idx & 63;
        float c = cosv[h], sn = sinv[h];
        int p = (d < 32) ? (2 * d + 1) : (2 * (d - 32));
        float sgn = (d < 32) ? -1.0f : 1.0f;
        float qv = __half2float(qg[idx]);
        float qp = __half2float(qg[h * 64 + p]);
        qs[h][d] = qv * c + sgn * qp * sn;
        float kv = __half2float(kg[idx]);
        float kp = __half2float(kg[h * 64 + p]);
        ks[h][d] = kv * c + sgn * kp * sn;
        vs[h][d] = __half2float(vg[idx]);
    }
    __syncthreads();

    // scores: each thread computes row i = tid>>2, 8 columns starting at (tid&3)*8
    {
        int i  = tid >> 2;
        int j0 = (tid & 3) * 8;
        float acc[8] = {0,0,0,0,0,0,0,0};
        #pragma unroll
        for (int d = 0; d < 64; d += 4) {
            float4 q4 = *(const float4*)&qs[i][d];
            #pragma unroll
            for (int jj = 0; jj < 8; jj++) {
                float4 k4 = *(const float4*)&ks[j0 + jj][d];
                acc[jj] += q4.x * k4.x + q4.y * k4.y + q4.z * k4.z + q4.w * k4.w;
            }
        }
        #pragma unroll
        for (int jj = 0; jj < 8; jj++)
            ss[i][j0 + jj] = acc[jj] * 0.125f;   // 1/sqrt(64)
    }
    __syncthreads();

    // softmax per row (threads 0..31)
    if (tid < 32) {
        float mx = -1e30f;
        #pragma unroll
        for (int j = 0; j < 32; j++) mx = fmaxf(mx, ss[tid][j]);
        float sum = 0.f;
        #pragma unroll
        for (int j = 0; j < 32; j++) {
            float e = expf(ss[tid][j] - mx);
            ss[tid][j] = e;
            sum += e;
        }
        float inv = 1.0f / sum;
        #pragma unroll
        for (int j = 0; j < 32; j++) ss[tid][j] *= inv;
    }
    __syncthreads();

    // out[i, d0..d0+15] = sum_j probs[i][j] * v[j][d]
    {
        int i  = tid >> 2;
        int d0 = (tid & 3) * 16;
        float acc[16];
        #pragma unroll
        for (int z = 0; z < 16; z++) acc[z] = 0.f;
        #pragma unroll
        for (int j = 0; j < 32; j++) {
            float p = ss[i][j];
            #pragma unroll
            for (int dd = 0; dd < 16; dd += 4) {
                float4 v4 = *(const float4*)&vs[j][d0 + dd];
                acc[dd]     += p * v4.x;
                acc[dd + 1] += p * v4.y;
                acc[dd + 2] += p * v4.z;
                acc[dd + 3] += p * v4.w;
            }
        }
        __half* og = g_attn + (size_t)t * HIDDEN + i * 64 + d0;
        #pragma unroll
        for (int dd = 0; dd < 16; dd += 2)
            *(__half2*)(og + dd) = __floats2half2_rn(acc[dd], acc[dd + 1]);
    }
}

// ---------------- launch ----------------
extern "C" void kernel_launch(void* const* d_in, const int* in_sizes, int n_in,
                              void* d_out, int out_size) {
    const float* hs    = (const float*)d_in[0];
    const float* w_q   = (const float*)d_in[1];
    const float* w_k   = (const float*)d_in[2];
    const float* w_v   = (const float*)d_in[3];
    const float* w_o   = (const float*)d_in[4];
    const float* gamma = (const float*)d_in[5];
    const float* beta  = (const float*)d_in[6];

    __half* wdev;
    cudaGetSymbolAddress((void**)&wdev, g_w);

    // 1) LayerNorm -> fp16 x
    ln_kernel<<<NTOK, 256>>>(hs, gamma, beta);

    // 2) convert weights to fp16
    {
        int grid = (HIDDEN * HIDDEN / 4) / 256;   // 4096
        cvt_kernel<<<grid, 256>>>(w_q, wdev + 0 * (size_t)HIDDEN * HIDDEN);
        cvt_kernel<<<grid, 256>>>(w_k, wdev + 1 * (size_t)HIDDEN * HIDDEN);
        cvt_kernel<<<grid, 256>>>(w_v, wdev + 2 * (size_t)HIDDEN * HIDDEN);
        cvt_kernel<<<grid, 256>>>(w_o, wdev + 3 * (size_t)HIDDEN * HIDDEN);
    }

    __half *xdev, *qkvdev, *attndev;
    cudaGetSymbolAddress((void**)&xdev, g_x);
    cudaGetSymbolAddress((void**)&qkvdev, g_qkv);
    cudaGetSymbolAddress((void**)&attndev, g_attn);

    size_t gemm_smem = BMT * LDA_S * sizeof(__half) + BKT * LDB_S * sizeof(__half); // 35840 B

    // 3) QKV GEMM: [32768, 6144] = x @ [wq|wk|wv]
    {
        dim3 grid(3 * HIDDEN / BNT, NTOK / BMT);  // (48, 256)
        gemm_kernel<true><<<grid, 256, gemm_smem>>>(xdev, qkvdev);
    }

    // 4) RoPE + per-token head attention
    attn_kernel<<<NTOK, 128>>>();

    // 5) Output GEMM: [32768, 2048] = attn @ w_o  (fp32 out)
    {
        dim3 grid(HIDDEN / BNT, NTOK / BMT);      // (16, 256)
        gemm_kernel<false><<<grid, 256, gemm_smem>>>(attndev, d_out);
    }
}

// round 7
// speedup vs baseline: 1.2118x; 1.2118x over previous
#include <cuda_runtime.h>
#include <cuda_fp16.h>
#include <stdint.h>

#define HIDDEN   2048
#define NHEADS   32
#define SEQ      4096
#define NTOK     32768           // B * S

// ---------------- scratch (static device globals; no allocation) ----------------
__device__ __half g_x[(size_t)NTOK * HIDDEN];              // LN output fp16     (128 MB)
__device__ __half g_wt[(size_t)4 * HIDDEN * HIDDEN];       // wq^T|wk^T|wv^T|wo^T fp16 (32 MB)
__device__ __half g_qkv[(size_t)NTOK * 3 * HIDDEN];        // q|k|v per token    (402 MB)
__device__ __half g_attn[(size_t)NTOK * HIDDEN];           // attn out fp16      (128 MB)

// ===================== PTX helpers (baseline sm_80+ features only) =====================
__device__ __forceinline__ uint32_t smem_u32(const void* p) {
    uint32_t a;
    asm("{ .reg .u64 t; cvta.to.shared.u64 t, %1; cvt.u32.u64 %0, t; }" : "=r"(a) : "l"(p));
    return a;
}
#define CP_ASYNC16(dst, src) \
    asm volatile("cp.async.cg.shared.global [%0], [%1], 16;" :: "r"(dst), "l"(src) : "memory")
#define CP_COMMIT() asm volatile("cp.async.commit_group;" ::: "memory")
#define CP_WAIT2()  asm volatile("cp.async.wait_group 2;" ::: "memory")

#define LDSM_X4(r0,r1,r2,r3, addr) \
    asm volatile("ldmatrix.sync.aligned.m8n8.x4.shared.b16 {%0,%1,%2,%3}, [%4];" \
        : "=r"(r0),"=r"(r1),"=r"(r2),"=r"(r3) : "r"(addr))
#define LDSM_X2(r0,r1, addr) \
    asm volatile("ldmatrix.sync.aligned.m8n8.x2.shared.b16 {%0,%1}, [%2];" \
        : "=r"(r0),"=r"(r1) : "r"(addr))

#define MMA16816(d, a0,a1,a2,a3, b0,b1) \
    asm volatile("mma.sync.aligned.m16n8k16.row.col.f32.f16.f16.f32 " \
        "{%0,%1,%2,%3}, {%4,%5,%6,%7}, {%8,%9}, {%0,%1,%2,%3};" \
        : "+f"((d)[0]),"+f"((d)[1]),"+f"((d)[2]),"+f"((d)[3]) \
        : "r"(a0),"r"(a1),"r"(a2),"r"(a3), "r"(b0),"r"(b1))

#define SWZ(off) ((off) ^ (((off) >> 3) & 0x70))

// ===================== LayerNorm -> fp16 =====================
__device__ __forceinline__ float warp_red(float v) {
    #pragma unroll
    for (int o = 16; o; o >>= 1) v += __shfl_xor_sync(0xffffffffu, v, o);
    return v;
}

__global__ __launch_bounds__(256) void ln_kernel(const float* __restrict__ hs,
                          const float* __restrict__ gamma,
                          const float* __restrict__ beta) {
    int t = blockIdx.x;
    int tid = threadIdx.x;
    const float4* row = (const float4*)(hs + (size_t)t * HIDDEN);
    float4 v0 = row[tid];
    float4 v1 = row[tid + 256];
    float s = v0.x + v0.y + v0.z + v0.w + v1.x + v1.y + v1.z + v1.w;
    float q = v0.x*v0.x + v0.y*v0.y + v0.z*v0.z + v0.w*v0.w
            + v1.x*v1.x + v1.y*v1.y + v1.z*v1.z + v1.w*v1.w;
    s = warp_red(s);
    q = warp_red(q);
    __shared__ float sh_s[8], sh_q[8];
    int w = tid >> 5, l = tid & 31;
    if (l == 0) { sh_s[w] = s; sh_q[w] = q; }
    __syncthreads();
    float st = 0.f, qt = 0.f;
    #pragma unroll
    for (int i = 0; i < 8; i++) { st += sh_s[i]; qt += sh_q[i]; }
    float mean = st * (1.0f / HIDDEN);
    float var  = qt * (1.0f / HIDDEN) - mean * mean;
    float rstd = rsqrtf(var + 1e-5f);

    const float4* g4 = (const float4*)gamma;
    const float4* b4 = (const float4*)beta;
    __half2* out = (__half2*)(g_x + (size_t)t * HIDDEN);
    {
        float4 g = g4[tid], b = b4[tid];
        out[2*tid]   = __floats2half2_rn((v0.x - mean)*rstd*g.x + b.x, (v0.y - mean)*rstd*g.y + b.y);
        out[2*tid+1] = __floats2half2_rn((v0.z - mean)*rstd*g.z + b.z, (v0.w - mean)*rstd*g.w + b.w);
    }
    {
        int i2 = tid + 256;
        float4 g = g4[i2], b = b4[i2];
        out[2*i2]   = __floats2half2_rn((v1.x - mean)*rstd*g.x + b.x, (v1.y - mean)*rstd*g.y + b.y);
        out[2*i2+1] = __floats2half2_rn((v1.z - mean)*rstd*g.z + b.z, (v1.w - mean)*rstd*g.w + b.w);
    }
}

// ===================== weight fp32 -> fp16, transposed =====================
__global__ __launch_bounds__(256) void cvt_t_kernel(const float* __restrict__ w, __half* __restrict__ o) {
    __shared__ float t[32][33];
    int bx = blockIdx.x * 32;   // n0
    int by = blockIdx.y * 32;   // k0
    int tx = threadIdx.x & 31, ty = threadIdx.x >> 5;
    #pragma unroll
    for (int r = 0; r < 32; r += 8)
        t[ty + r][tx] = w[(size_t)(by + ty + r) * HIDDEN + bx + tx];
    __syncthreads();
    #pragma unroll
    for (int r = 0; r < 32; r += 8)
        o[(size_t)(bx + ty + r) * HIDDEN + by + tx] = __float2half_rn(t[tx][ty + r]);
}

// ===================== pipelined mma.sync GEMM =====================
// C[M,N] = A[M,2048] @ BW^T, BW stored [N,2048] k-contiguous.
// BM=128, BN=256, BK=64. 512 threads = 16 warps (2 along M x 8 along N), warp tile 64x32.
// 4-stage cp.async ring. SW128 swizzle on 128B smem rows.
#define BM 128
#define BN 256
#define BK 64
#define NSTG 4
#define NKT  (HIDDEN / BK)             // 32
#define TILE_A   (BM * 128)            // 16384 B
#define TILE_B   (BN * 128)            // 32768 B
#define STG_BYTES (TILE_A + TILE_B)    // 49152
#define GEMM_SMEM (NSTG * STG_BYTES)   // 196608

__device__ __forceinline__ void load_stage(uint32_t as, uint32_t bs,
                                           const __half* __restrict__ Arow,
                                           const __half* __restrict__ Brow,
                                           int kt, int tid) {
    const __half* a = Arow + kt * BK;
    const __half* b = Brow + kt * BK;
    #pragma unroll
    for (int j = 0; j < 2; j++) {                 // A: 1024 chunks of 16B
        int c = tid + j * 512;
        int r = c >> 3, k16 = c & 7;
        uint32_t off = (uint32_t)(r * 128 + k16 * 16);
        CP_ASYNC16(as + SWZ(off), (const char*)(a + (size_t)r * HIDDEN) + k16 * 16);
    }
    #pragma unroll
    for (int j = 0; j < 4; j++) {                 // B: 2048 chunks of 16B
        int c = tid + j * 512;
        int r = c >> 3, k16 = c & 7;
        uint32_t off = (uint32_t)(r * 128 + k16 * 16);
        CP_ASYNC16(bs + SWZ(off), (const char*)(b + (size_t)r * HIDDEN) + k16 * 16);
    }
}

template<bool QKV>
__global__ __launch_bounds__(512, 1) void gemm_mma(const __half* __restrict__ A,
                                                   const __half* __restrict__ BW,
                                                   void* __restrict__ Cout) {
    extern __shared__ char smem[];
    uint32_t sb = smem_u32(smem);
    int tid = threadIdx.x;
    int wid = tid >> 5, lane = tid & 31;
    int warp_m = (wid >> 3) * 64;      // 0 or 64
    int warp_n = (wid & 7) * 32;       // 0..224
    int m0 = blockIdx.y * BM;
    int n0 = blockIdx.x * BN;

    const __half* Arow = A + (size_t)m0 * HIDDEN;
    const __half* Brow;
    if (QKV) Brow = BW + ((size_t)(n0 >> 11) << 22) + (size_t)(n0 & 2047) * HIDDEN;
    else     Brow = BW + (size_t)n0 * HIDDEN;

    float acc[4][4][4];
    #pragma unroll
    for (int mt = 0; mt < 4; mt++)
        #pragma unroll
        for (int nt = 0; nt < 4; nt++)
            #pragma unroll
            for (int z = 0; z < 4; z++) acc[mt][nt][z] = 0.f;

    // prologue: stages 0..2 <- tiles 0..2
    #pragma unroll
    for (int s = 0; s < NSTG - 1; s++) {
        uint32_t base = sb + s * STG_BYTES;
        load_stage(base, base + TILE_A, Arow, Brow, s, tid);
        CP_COMMIT();
    }

    // per-lane ldmatrix row indices (fixed across k)
    int a_row = warp_m + (lane & 15);          // + mt*16
    int a_kg  = (lane >> 4) * 16;              // 0 or 16 bytes
    int b_row = warp_n + (lane & 7);           // + nt*8
    int b_kg  = ((lane >> 3) & 1) * 16;        // 0 or 16 bytes

    for (int i = 0; i < NKT; i++) {
        int s = i & (NSTG - 1);
        CP_WAIT2();
        __syncthreads();

        // issue loads for tile i+3 into stage (i+3)%4 (freed at iter i-1, safe after sync)
        if (i + NSTG - 1 < NKT) {
            int sn = (i + NSTG - 1) & (NSTG - 1);
            uint32_t base = sb + sn * STG_BYTES;
            load_stage(base, base + TILE_A, Arow, Brow, i + NSTG - 1, tid);
        }
        CP_COMMIT();

        uint32_t as_base = sb + s * STG_BYTES;
        uint32_t bs_base = as_base + TILE_A;

        #pragma unroll
        for (int ks = 0; ks < 4; ks++) {
            uint32_t a_frag[4][4];
            uint32_t b_frag[4][2];
            #pragma unroll
            for (int mt = 0; mt < 4; mt++) {
                uint32_t off = (uint32_t)((a_row + mt * 16) * 128 + ks * 32 + a_kg);
                LDSM_X4(a_frag[mt][0], a_frag[mt][1], a_frag[mt][2], a_frag[mt][3],
                        as_base + SWZ(off));
            }
            #pragma unroll
            for (int nt = 0; nt < 4; nt++) {
                uint32_t off = (uint32_t)((b_row + nt * 8) * 128 + ks * 32 + b_kg);
                LDSM_X2(b_frag[nt][0], b_frag[nt][1], bs_base + SWZ(off));
            }
            #pragma unroll
            for (int mt = 0; mt < 4; mt++)
                #pragma unroll
                for (int nt = 0; nt < 4; nt++)
                    MMA16816(acc[mt][nt],
                             a_frag[mt][0], a_frag[mt][1], a_frag[mt][2], a_frag[mt][3],
                             b_frag[nt][0], b_frag[nt][1]);
        }
    }

    // ---- epilogue: regs -> gmem ----
    int r_base = m0 + warp_m + (lane >> 2);
    int c_base = n0 + warp_n + (lane & 3) * 2;
    #pragma unroll
    for (int mt = 0; mt < 4; mt++) {
        #pragma unroll
        for (int nt = 0; nt < 4; nt++) {
            int row0 = r_base + mt * 16;
            int col  = c_base + nt * 8;
            if (QKV) {
                __half* d0 = (__half*)Cout + (size_t)row0 * (3 * HIDDEN) + col;
                __half* d1 = d0 + (size_t)8 * (3 * HIDDEN);
                *(__half2*)d0 = __floats2half2_rn(acc[mt][nt][0], acc[mt][nt][1]);
                *(__half2*)d1 = __floats2half2_rn(acc[mt][nt][2], acc[mt][nt][3]);
            } else {
                float* d0 = (float*)Cout + (size_t)row0 * HIDDEN + col;
                float* d1 = d0 + (size_t)8 * HIDDEN;
                *(float2*)d0 = make_float2(acc[mt][nt][0], acc[mt][nt][1]);
                *(float2*)d1 = make_float2(acc[mt][nt][2], acc[mt][nt][3]);
            }
        }
    }
}

// ===================== per-token RoPE + 32x32 head-attention =====================
__global__ __launch_bounds__(128) void attn_kernel() {
    int t = blockIdx.x;
    int s = t & (SEQ - 1);
    int tid = threadIdx.x;

    __shared__ float qs[32][68], ks[32][68], vs[32][68];
    __shared__ float ss[32][33];
    __shared__ float cosv[32], sinv[32];

    if (tid < 32) {
        float e = (float)(2 * tid) / 64.0f;
        float p = powf(10000.0f, e);
        float ang = (float)s * (1.0f / p);
        sinv[tid] = sinf(ang);
        cosv[tid] = cosf(ang);
    }
    __syncthreads();

    const __half* qg = g_qkv + (size_t)t * (3 * HIDDEN);
    const __half* kg = qg + HIDDEN;
    const __half* vg = qg + 2 * HIDDEN;

    #pragma unroll
    for (int idx = tid; idx < HIDDEN; idx += 128) {
        int h = idx >> 6, d = idx & 63;
        float c = cosv[h], sn = sinv[h];
        int p = (d < 32) ? (2 * d + 1) : (2 * (d - 32));
        float sgn = (d < 32) ? -1.0f : 1.0f;
        float qv = __half2float(qg[idx]);
        float qp = __half2float(qg[h * 64 + p]);
        qs[h][d] = qv * c + sgn * qp * sn;
        float kv = __half2float(kg[idx]);
        float kp = __half2float(kg[h * 64 + p]);
        ks[h][d] = kv * c + sgn * kp * sn;
        vs[h][d] = __half2float(vg[idx]);
    }
    __syncthreads();

    {
        int i  = tid >> 2;
        int j0 = (tid & 3) * 8;
        float acc[8] = {0,0,0,0,0,0,0,0};
        #pragma unroll
        for (int d = 0; d < 64; d += 4) {
            float4 q4 = *(const float4*)&qs[i][d];
            #pragma unroll
            for (int jj = 0; jj < 8; jj++) {
                float4 k4 = *(const float4*)&ks[j0 + jj][d];
                acc[jj] += q4.x * k4.x + q4.y * k4.y + q4.z * k4.z + q4.w * k4.w;
            }
        }
        #pragma unroll
        for (int jj = 0; jj < 8; jj++)
            ss[i][j0 + jj] = acc[jj] * 0.125f;
    }
    __syncthreads();

    if (tid < 32) {
        float mx = -1e30f;
        #pragma unroll
        for (int j = 0; j < 32; j++) mx = fmaxf(mx, ss[tid][j]);
        float sum = 0.f;
        #pragma unroll
        for (int j = 0; j < 32; j++) {
            float e = expf(ss[tid][j] - mx);
            ss[tid][j] = e;
            sum += e;
        }
        float inv = 1.0f / sum;
        #pragma unroll
        for (int j = 0; j < 32; j++) ss[tid][j] *= inv;
    }
    __syncthreads();

    {
        int i  = tid >> 2;
        int d0 = (tid & 3) * 16;
        float acc[16];
        #pragma unroll
        for (int z = 0; z < 16; z++) acc[z] = 0.f;
        #pragma unroll
        for (int j = 0; j < 32; j++) {
            float p = ss[i][j];
            #pragma unroll
            for (int dd = 0; dd < 16; dd += 4) {
                float4 v4 = *(const float4*)&vs[j][d0 + dd];
                acc[dd]     += p * v4.x;
                acc[dd + 1] += p * v4.y;
                acc[dd + 2] += p * v4.z;
                acc[dd + 3] += p * v4.w;
            }
        }
        __half* og = g_attn + (size_t)t * HIDDEN + i * 64 + d0;
        #pragma unroll
        for (int dd = 0; dd < 16; dd += 2)
            *(__half2*)(og + dd) = __floats2half2_rn(acc[dd], acc[dd + 1]);
    }
}

// ===================== launch =====================
extern "C" void kernel_launch(void* const* d_in, const int* in_sizes, int n_in,
                              void* d_out, int out_size) {
    const float* hs    = (const float*)d_in[0];
    const float* w_q   = (const float*)d_in[1];
    const float* w_k   = (const float*)d_in[2];
    const float* w_v   = (const float*)d_in[3];
    const float* w_o   = (const float*)d_in[4];
    const float* gamma = (const float*)d_in[5];
    const float* beta  = (const float*)d_in[6];

    __half *xdev, *wtdev, *qkvdev, *attndev;
    cudaGetSymbolAddress((void**)&xdev, g_x);
    cudaGetSymbolAddress((void**)&wtdev, g_wt);
    cudaGetSymbolAddress((void**)&qkvdev, g_qkv);
    cudaGetSymbolAddress((void**)&attndev, g_attn);

    cudaFuncSetAttribute(gemm_mma<true>,  cudaFuncAttributeMaxDynamicSharedMemorySize, GEMM_SMEM);
    cudaFuncSetAttribute(gemm_mma<false>, cudaFuncAttributeMaxDynamicSharedMemorySize, GEMM_SMEM);

    // 1) LayerNorm -> fp16
    ln_kernel<<<NTOK, 256>>>(hs, gamma, beta);

    // 2) weights: fp32 -> fp16 transposed ([n][k])
    {
        dim3 grid(HIDDEN / 32, HIDDEN / 32);
        cvt_t_kernel<<<grid, 256>>>(w_q, wtdev + 0 * (size_t)HIDDEN * HIDDEN);
        cvt_t_kernel<<<grid, 256>>>(w_k, wtdev + 1 * (size_t)HIDDEN * HIDDEN);
        cvt_t_kernel<<<grid, 256>>>(w_v, wtdev + 2 * (size_t)HIDDEN * HIDDEN);
        cvt_t_kernel<<<grid, 256>>>(w_o, wtdev + 3 * (size_t)HIDDEN * HIDDEN);
    }

    // 3) QKV GEMM: [32768, 6144] fp16
    {
        dim3 grid(3 * HIDDEN / BN, NTOK / BM);   // (24, 256)
        gemm_mma<true><<<grid, 512, GEMM_SMEM>>>(xdev, wtdev, qkvdev);
    }

    // 4) RoPE + per-token head attention
    attn_kernel<<<NTOK, 128>>>();

    // 5) Output GEMM: [32768, 2048] fp32 -> d_out
    {
        dim3 grid(HIDDEN / BN, NTOK / BM);       // (8, 256)
        gemm_mma<false><<<grid, 512, GEMM_SMEM>>>(attndev, wtdev + 3 * (size_t)HIDDEN * HIDDEN, d_out);
    }
}

// round 9
// speedup vs baseline: 1.2820x; 1.0580x over previous
#include <cuda_runtime.h>
#include <cuda_fp16.h>
#include <stdint.h>

#define HIDDEN   2048
#define NHEADS   32
#define SEQ      4096
#define NTOK     32768           // B * S

// ---------------- scratch (static device globals; no allocation) ----------------
__device__ __half g_x[(size_t)NTOK * HIDDEN];              // LN output fp16     (128 MB)
__device__ __half g_wt[(size_t)4 * HIDDEN * HIDDEN];       // wq^T|wk^T|wv^T|wo^T fp16 (32 MB)
__device__ __half g_qkv[(size_t)NTOK * 3 * HIDDEN];        // q|k|v per token    (402 MB)
__device__ __half g_attn[(size_t)NTOK * HIDDEN];           // attn out fp16      (128 MB)

// ===================== PTX helpers (baseline sm_80+ features only) =====================
__device__ __forceinline__ uint32_t smem_u32(const void* p) {
    uint32_t a;
    asm("{ .reg .u64 t; cvta.to.shared.u64 t, %1; cvt.u32.u64 %0, t; }" : "=r"(a) : "l"(p));
    return a;
}
#define CP_ASYNC16(dst, src) \
    asm volatile("cp.async.cg.shared.global [%0], [%1], 16;" :: "r"(dst), "l"(src) : "memory")
#define CP_COMMIT() asm volatile("cp.async.commit_group;" ::: "memory")
#define CP_WAIT1()  asm volatile("cp.async.wait_group 1;" ::: "memory")

#define LDSM_X4(r0,r1,r2,r3, addr) \
    asm volatile("ldmatrix.sync.aligned.m8n8.x4.shared.b16 {%0,%1,%2,%3}, [%4];" \
        : "=r"(r0),"=r"(r1),"=r"(r2),"=r"(r3) : "r"(addr))
#define LDSM_X2(r0,r1, addr) \
    asm volatile("ldmatrix.sync.aligned.m8n8.x2.shared.b16 {%0,%1}, [%2];" \
        : "=r"(r0),"=r"(r1) : "r"(addr))

#define MMA16816(d, a0,a1,a2,a3, b0,b1) \
    asm volatile("mma.sync.aligned.m16n8k16.row.col.f32.f16.f16.f32 " \
        "{%0,%1,%2,%3}, {%4,%5,%6,%7}, {%8,%9}, {%0,%1,%2,%3};" \
        : "+f"((d)[0]),"+f"((d)[1]),"+f"((d)[2]),"+f"((d)[3]) \
        : "r"(a0),"r"(a1),"r"(a2),"r"(a3), "r"(b0),"r"(b1))

#define SWZ(off) ((off) ^ (((off) >> 3) & 0x70))

// ===================== LayerNorm -> fp16 =====================
__device__ __forceinline__ float warp_red(float v) {
    #pragma unroll
    for (int o = 16; o; o >>= 1) v += __shfl_xor_sync(0xffffffffu, v, o);
    return v;
}

__global__ __launch_bounds__(256) void ln_kernel(const float* __restrict__ hs,
                          const float* __restrict__ gamma,
                          const float* __restrict__ beta) {
    int t = blockIdx.x;
    int tid = threadIdx.x;
    const float4* row = (const float4*)(hs + (size_t)t * HIDDEN);
    float4 v0 = row[tid];
    float4 v1 = row[tid + 256];
    float s = v0.x + v0.y + v0.z + v0.w + v1.x + v1.y + v1.z + v1.w;
    float q = v0.x*v0.x + v0.y*v0.y + v0.z*v0.z + v0.w*v0.w
            + v1.x*v1.x + v1.y*v1.y + v1.z*v1.z + v1.w*v1.w;
    s = warp_red(s);
    q = warp_red(q);
    __shared__ float sh_s[8], sh_q[8];
    int w = tid >> 5, l = tid & 31;
    if (l == 0) { sh_s[w] = s; sh_q[w] = q; }
    __syncthreads();
    float st = 0.f, qt = 0.f;
    #pragma unroll
    for (int i = 0; i < 8; i++) { st += sh_s[i]; qt += sh_q[i]; }
    float mean = st * (1.0f / HIDDEN);
    float var  = qt * (1.0f / HIDDEN) - mean * mean;
    float rstd = rsqrtf(var + 1e-5f);

    const float4* g4 = (const float4*)gamma;
    const float4* b4 = (const float4*)beta;
    __half2* out = (__half2*)(g_x + (size_t)t * HIDDEN);
    {
        float4 g = g4[tid], b = b4[tid];
        out[2*tid]   = __floats2half2_rn((v0.x - mean)*rstd*g.x + b.x, (v0.y - mean)*rstd*g.y + b.y);
        out[2*tid+1] = __floats2half2_rn((v0.z - mean)*rstd*g.z + b.z, (v0.w - mean)*rstd*g.w + b.w);
    }
    {
        int i2 = tid + 256;
        float4 g = g4[i2], b = b4[i2];
        out[2*i2]   = __floats2half2_rn((v1.x - mean)*rstd*g.x + b.x, (v1.y - mean)*rstd*g.y + b.y);
        out[2*i2+1] = __floats2half2_rn((v1.z - mean)*rstd*g.z + b.z, (v1.w - mean)*rstd*g.w + b.w);
    }
}

// ===================== weight fp32 -> fp16, transposed =====================
__global__ __launch_bounds__(256) void cvt_t_kernel(const float* __restrict__ w, __half* __restrict__ o) {
    __shared__ float t[32][33];
    int bx = blockIdx.x * 32;   // n0
    int by = blockIdx.y * 32;   // k0
    int tx = threadIdx.x & 31, ty = threadIdx.x >> 5;
    #pragma unroll
    for (int r = 0; r < 32; r += 8)
        t[ty + r][tx] = w[(size_t)(by + ty + r) * HIDDEN + bx + tx];
    __syncthreads();
    #pragma unroll
    for (int r = 0; r < 32; r += 8)
        o[(size_t)(bx + ty + r) * HIDDEN + by + tx] = __float2half_rn(t[tx][ty + r]);
}

// ===================== pipelined mma.sync GEMM =====================
// C[M,N] = A[M,2048] @ BW^T, BW stored [N,2048] k-contiguous.
// BM=128, BN=128, BK=64. 128 threads = 4 warps (2x2), warp tile 64x64.
// 3-stage cp.async ring (96KB smem) -> 2 CTAs/SM for overlap.
#define BM 128
#define BN 128
#define BK 64
#define NSTG 3
#define NKT  (HIDDEN / BK)             // 32
#define TILE_A   (BM * 128)            // 16384 B
#define TILE_B   (BN * 128)            // 16384 B
#define STG_BYTES (TILE_A + TILE_B)    // 32768
#define GEMM_SMEM (NSTG * STG_BYTES)   // 98304

__device__ __forceinline__ void load_stage(uint32_t as, uint32_t bs,
                                           const __half* __restrict__ Arow,
                                           const __half* __restrict__ Brow,
                                           int kt, int tid) {
    const __half* a = Arow + kt * BK;
    const __half* b = Brow + kt * BK;
    #pragma unroll
    for (int j = 0; j < 8; j++) {                 // A: 1024 chunks of 16B
        int c = tid + j * 128;
        int r = c >> 3, k16 = c & 7;
        uint32_t off = (uint32_t)(r * 128 + k16 * 16);
        CP_ASYNC16(as + SWZ(off), (const char*)(a + (size_t)r * HIDDEN) + k16 * 16);
    }
    #pragma unroll
    for (int j = 0; j < 8; j++) {                 // B: 1024 chunks of 16B
        int c = tid + j * 128;
        int r = c >> 3, k16 = c & 7;
        uint32_t off = (uint32_t)(r * 128 + k16 * 16);
        CP_ASYNC16(bs + SWZ(off), (const char*)(b + (size_t)r * HIDDEN) + k16 * 16);
    }
}

template<bool QKV>
__global__ __launch_bounds__(128, 2) void gemm_mma(const __half* __restrict__ A,
                                                   const __half* __restrict__ BW,
                                                   void* __restrict__ Cout) {
    extern __shared__ char smem[];
    uint32_t sb = smem_u32(smem);
    int tid = threadIdx.x;
    int wid = tid >> 5, lane = tid & 31;
    int warp_m = (wid >> 1) * 64;      // 0 or 64
    int warp_n = (wid & 1) * 64;       // 0 or 64
    int m0 = blockIdx.y * BM;
    int n0 = blockIdx.x * BN;

    const __half* Arow = A + (size_t)m0 * HIDDEN;
    const __half* Brow;
    if (QKV) Brow = BW + ((size_t)(n0 >> 11) << 22) + (size_t)(n0 & 2047) * HIDDEN;
    else     Brow = BW + (size_t)n0 * HIDDEN;

    float acc[4][8][4];
    #pragma unroll
    for (int mt = 0; mt < 4; mt++)
        #pragma unroll
        for (int nt = 0; nt < 8; nt++)
            #pragma unroll
            for (int z = 0; z < 4; z++) acc[mt][nt][z] = 0.f;

    // prologue: stages 0,1 <- tiles 0,1
    #pragma unroll
    for (int s = 0; s < NSTG - 1; s++) {
        uint32_t base = sb + s * STG_BYTES;
        load_stage(base, base + TILE_A, Arow, Brow, s, tid);
        CP_COMMIT();
    }

    // per-lane ldmatrix indices (fixed across k)
    int a_row = warp_m + (lane & 15);          // + mt*16
    int a_kg  = (lane >> 4) * 16;              // 0 or 16 bytes
    int b_row = warp_n + (lane & 7);           // + nt*8
    int b_kg  = ((lane >> 3) & 1) * 16;        // 0 or 16 bytes

    for (int i = 0; i < NKT; i++) {
        int s = i % NSTG;
        CP_WAIT1();
        __syncthreads();

        // prefetch tile i+2 into stage (i+2)%3 (consumed at iter i-1; safe after sync)
        if (i + NSTG - 1 < NKT) {
            int sn = (i + NSTG - 1) % NSTG;
            uint32_t base = sb + sn * STG_BYTES;
            load_stage(base, base + TILE_A, Arow, Brow, i + NSTG - 1, tid);
        }
        CP_COMMIT();

        uint32_t as_base = sb + s * STG_BYTES;
        uint32_t bs_base = as_base + TILE_A;

        #pragma unroll
        for (int ks = 0; ks < 4; ks++) {
            uint32_t a_frag[4][4];
            uint32_t b_frag[8][2];
            #pragma unroll
            for (int mt = 0; mt < 4; mt++) {
                uint32_t off = (uint32_t)((a_row + mt * 16) * 128 + ks * 32 + a_kg);
                LDSM_X4(a_frag[mt][0], a_frag[mt][1], a_frag[mt][2], a_frag[mt][3],
                        as_base + SWZ(off));
            }
            #pragma unroll
            for (int nt = 0; nt < 8; nt++) {
                uint32_t off = (uint32_t)((b_row + nt * 8) * 128 + ks * 32 + b_kg);
                LDSM_X2(b_frag[nt][0], b_frag[nt][1], bs_base + SWZ(off));
            }
            #pragma unroll
            for (int mt = 0; mt < 4; mt++)
                #pragma unroll
                for (int nt = 0; nt < 8; nt++)
                    MMA16816(acc[mt][nt],
                             a_frag[mt][0], a_frag[mt][1], a_frag[mt][2], a_frag[mt][3],
                             b_frag[nt][0], b_frag[nt][1]);
        }
    }

    // ---- epilogue: regs -> gmem ----
    int r_base = m0 + warp_m + (lane >> 2);
    int c_base = n0 + warp_n + (lane & 3) * 2;
    #pragma unroll
    for (int mt = 0; mt < 4; mt++) {
        #pragma unroll
        for (int nt = 0; nt < 8; nt++) {
            int row0 = r_base + mt * 16;
            int col  = c_base + nt * 8;
            if (QKV) {
                __half* d0 = (__half*)Cout + (size_t)row0 * (3 * HIDDEN) + col;
                __half* d1 = d0 + (size_t)8 * (3 * HIDDEN);
                *(__half2*)d0 = __floats2half2_rn(acc[mt][nt][0], acc[mt][nt][1]);
                *(__half2*)d1 = __floats2half2_rn(acc[mt][nt][2], acc[mt][nt][3]);
            } else {
                float* d0 = (float*)Cout + (size_t)row0 * HIDDEN + col;
                float* d1 = d0 + (size_t)8 * HIDDEN;
                *(float2*)d0 = make_float2(acc[mt][nt][0], acc[mt][nt][1]);
                *(float2*)d1 = make_float2(acc[mt][nt][2], acc[mt][nt][3]);
            }
        }
    }
}

// ===================== per-token RoPE + 32x32 head-attention =====================
__global__ __launch_bounds__(128) void attn_kernel() {
    int t = blockIdx.x;
    int s = t & (SEQ - 1);
    int tid = threadIdx.x;

    __shared__ float qs[32][68], ks[32][68], vs[32][68];
    __shared__ float ss[32][33];
    __shared__ float cosv[32], sinv[32];

    if (tid < 32) {
        float e = (float)(2 * tid) / 64.0f;
        float p = powf(10000.0f, e);
        float ang = (float)s * (1.0f / p);
        sinv[tid] = sinf(ang);
        cosv[tid] = cosf(ang);
    }
    __syncthreads();

    const __half* qg = g_qkv + (size_t)t * (3 * HIDDEN);
    const __half* kg = qg + HIDDEN;
    const __half* vg = qg + 2 * HIDDEN;

    #pragma unroll
    for (int idx = tid; idx < HIDDEN; idx += 128) {
        int h = idx >> 6, d = idx & 63;
        float c = cosv[h], sn = sinv[h];
        int p = (d < 32) ? (2 * d + 1) : (2 * (d - 32));
        float sgn = (d < 32) ? -1.0f : 1.0f;
        float qv = __half2float(qg[idx]);
        float qp = __half2float(qg[h * 64 + p]);
        qs[h][d] = qv * c + sgn * qp * sn;
        float kv = __half2float(kg[idx]);
        float kp = __half2float(kg[h * 64 + p]);
        ks[h][d] = kv * c + sgn * kp * sn;
        vs[h][d] = __half2float(vg[idx]);
    }
    __syncthreads();

    {
        int i  = tid >> 2;
        int j0 = (tid & 3) * 8;
        float acc[8] = {0,0,0,0,0,0,0,0};
        #pragma unroll
        for (int d = 0; d < 64; d += 4) {
            float4 q4 = *(const float4*)&qs[i][d];
            #pragma unroll
            for (int jj = 0; jj < 8; jj++) {
                float4 k4 = *(const float4*)&ks[j0 + jj][d];
                acc[jj] += q4.x * k4.x + q4.y * k4.y + q4.z * k4.z + q4.w * k4.w;
            }
        }
        #pragma unroll
        for (int jj = 0; jj < 8; jj++)
            ss[i][j0 + jj] = acc[jj] * 0.125f;
    }
    __syncthreads();

    if (tid < 32) {
        float mx = -1e30f;
        #pragma unroll
        for (int j = 0; j < 32; j++) mx = fmaxf(mx, ss[tid][j]);
        float sum = 0.f;
        #pragma unroll
        for (int j = 0; j < 32; j++) {
            float e = expf(ss[tid][j] - mx);
            ss[tid][j] = e;
            sum += e;
        }
        float inv = 1.0f / sum;
        #pragma unroll
        for (int j = 0; j < 32; j++) ss[tid][j] *= inv;
    }
    __syncthreads();

    {
        int i  = tid >> 2;
        int d0 = (tid & 3) * 16;
        float acc[16];
        #pragma unroll
        for (int z = 0; z < 16; z++) acc[z] = 0.f;
        #pragma unroll
        for (int j = 0; j < 32; j++) {
            float p = ss[i][j];
            #pragma unroll
            for (int dd = 0; dd < 16; dd += 4) {
                float4 v4 = *(const float4*)&vs[j][d0 + dd];
                acc[dd]     += p * v4.x;
                acc[dd + 1] += p * v4.y;
                acc[dd + 2] += p * v4.z;
                acc[dd + 3] += p * v4.w;
            }
        }
        __half* og = g_attn + (size_t)t * HIDDEN + i * 64 + d0;
        #pragma unroll
        for (int dd = 0; dd < 16; dd += 2)
            *(__half2*)(og + dd) = __floats2half2_rn(acc[dd], acc[dd + 1]);
    }
}

// ===================== launch =====================
extern "C" void kernel_launch(void* const* d_in, const int* in_sizes, int n_in,
                              void* d_out, int out_size) {
    const float* hs    = (const float*)d_in[0];
    const float* w_q   = (const float*)d_in[1];
    const float* w_k   = (const float*)d_in[2];
    const float* w_v   = (const float*)d_in[3];
    const float* w_o   = (const float*)d_in[4];
    const float* gamma = (const float*)d_in[5];
    const float* beta  = (const float*)d_in[6];

    __half *xdev, *wtdev, *qkvdev, *attndev;
    cudaGetSymbolAddress((void**)&xdev, g_x);
    cudaGetSymbolAddress((void**)&wtdev, g_wt);
    cudaGetSymbolAddress((void**)&qkvdev, g_qkv);
    cudaGetSymbolAddress((void**)&attndev, g_attn);

    cudaFuncSetAttribute(gemm_mma<true>,  cudaFuncAttributeMaxDynamicSharedMemorySize, GEMM_SMEM);
    cudaFuncSetAttribute(gemm_mma<false>, cudaFuncAttributeMaxDynamicSharedMemorySize, GEMM_SMEM);

    // 1) LayerNorm -> fp16
    ln_kernel<<<NTOK, 256>>>(hs, gamma, beta);

    // 2) weights: fp32 -> fp16 transposed ([n][k])
    {
        dim3 grid(HIDDEN / 32, HIDDEN / 32);
        cvt_t_kernel<<<grid, 256>>>(w_q, wtdev + 0 * (size_t)HIDDEN * HIDDEN);
        cvt_t_kernel<<<grid, 256>>>(w_k, wtdev + 1 * (size_t)HIDDEN * HIDDEN);
        cvt_t_kernel<<<grid, 256>>>(w_v, wtdev + 2 * (size_t)HIDDEN * HIDDEN);
        cvt_t_kernel<<<grid, 256>>>(w_o, wtdev + 3 * (size_t)HIDDEN * HIDDEN);
    }

    // 3) QKV GEMM: [32768, 6144] fp16
    {
        dim3 grid(3 * HIDDEN / BN, NTOK / BM);   // (48, 256)
        gemm_mma<true><<<grid, 128, GEMM_SMEM>>>(xdev, wtdev, qkvdev);
    }

    // 4) RoPE + per-token head attention
    attn_kernel<<<NTOK, 128>>>();

    // 5) Output GEMM: [32768, 2048] fp32 -> d_out
    {
        dim3 grid(HIDDEN / BN, NTOK / BM);       // (16, 256)
        gemm_mma<false><<<grid, 128, GEMM_SMEM>>>(attndev, wtdev + 3 * (size_t)HIDDEN * HIDDEN, d_out);
    }
}

// round 11
// speedup vs baseline: 1.3504x; 1.0534x over previous
#include <cuda_runtime.h>
#include <cuda_fp16.h>
#include <stdint.h>

#define HIDDEN   2048
#define NHEADS   32
#define SEQ      4096
#define NTOK     32768           // B * S

// ---------------- scratch (static device globals; no allocation) ----------------
__device__ __half g_x[(size_t)NTOK * HIDDEN];              // LN output fp16     (128 MB)
__device__ __half g_wt[(size_t)4 * HIDDEN * HIDDEN];       // wq^T|wk^T|wv^T|wo^T fp16 (32 MB)
__device__ __half g_qkv[(size_t)NTOK * 3 * HIDDEN];        // q|k|v per token    (402 MB)
__device__ __half g_attn[(size_t)NTOK * HIDDEN];           // attn out fp16      (128 MB)

// ===================== PTX helpers (baseline sm_80+ features only) =====================
__device__ __forceinline__ uint32_t smem_u32(const void* p) {
    uint32_t a;
    asm("{ .reg .u64 t; cvta.to.shared.u64 t, %1; cvt.u32.u64 %0, t; }" : "=r"(a) : "l"(p));
    return a;
}
#define CP_ASYNC16(dst, src) \
    asm volatile("cp.async.cg.shared.global [%0], [%1], 16;" :: "r"(dst), "l"(src) : "memory")
#define CP_COMMIT() asm volatile("cp.async.commit_group;" ::: "memory")
#define CP_WAIT1()  asm volatile("cp.async.wait_group 1;" ::: "memory")

#define LDSM_X4(r0,r1,r2,r3, addr) \
    asm volatile("ldmatrix.sync.aligned.m8n8.x4.shared.b16 {%0,%1,%2,%3}, [%4];" \
        : "=r"(r0),"=r"(r1),"=r"(r2),"=r"(r3) : "r"(addr))

#define MMA16816(d, a0,a1,a2,a3, b0,b1) \
    asm volatile("mma.sync.aligned.m16n8k16.row.col.f32.f16.f16.f32 " \
        "{%0,%1,%2,%3}, {%4,%5,%6,%7}, {%8,%9}, {%0,%1,%2,%3};" \
        : "+f"((d)[0]),"+f"((d)[1]),"+f"((d)[2]),"+f"((d)[3]) \
        : "r"(a0),"r"(a1),"r"(a2),"r"(a3), "r"(b0),"r"(b1))

#define SWZ(off) ((off) ^ (((off) >> 3) & 0x70))

// ===================== LayerNorm -> fp16 =====================
__device__ __forceinline__ float warp_red(float v) {
    #pragma unroll
    for (int o = 16; o; o >>= 1) v += __shfl_xor_sync(0xffffffffu, v, o);
    return v;
}

__global__ __launch_bounds__(256) void ln_kernel(const float* __restrict__ hs,
                          const float* __restrict__ gamma,
                          const float* __restrict__ beta) {
    int t = blockIdx.x;
    int tid = threadIdx.x;
    const float4* row = (const float4*)(hs + (size_t)t * HIDDEN);
    float4 v0 = row[tid];
    float4 v1 = row[tid + 256];
    float s = v0.x + v0.y + v0.z + v0.w + v1.x + v1.y + v1.z + v1.w;
    float q = v0.x*v0.x + v0.y*v0.y + v0.z*v0.z + v0.w*v0.w
            + v1.x*v1.x + v1.y*v1.y + v1.z*v1.z + v1.w*v1.w;
    s = warp_red(s);
    q = warp_red(q);
    __shared__ float sh_s[8], sh_q[8];
    int w = tid >> 5, l = tid & 31;
    if (l == 0) { sh_s[w] = s; sh_q[w] = q; }
    __syncthreads();
    float st = 0.f, qt = 0.f;
    #pragma unroll
    for (int i = 0; i < 8; i++) { st += sh_s[i]; qt += sh_q[i]; }
    float mean = st * (1.0f / HIDDEN);
    float var  = qt * (1.0f / HIDDEN) - mean * mean;
    float rstd = rsqrtf(var + 1e-5f);

    const float4* g4 = (const float4*)gamma;
    const float4* b4 = (const float4*)beta;
    __half2* out = (__half2*)(g_x + (size_t)t * HIDDEN);
    {
        float4 g = g4[tid], b = b4[tid];
        out[2*tid]   = __floats2half2_rn((v0.x - mean)*rstd*g.x + b.x, (v0.y - mean)*rstd*g.y + b.y);
        out[2*tid+1] = __floats2half2_rn((v0.z - mean)*rstd*g.z + b.z, (v0.w - mean)*rstd*g.w + b.w);
    }
    {
        int i2 = tid + 256;
        float4 g = g4[i2], b = b4[i2];
        out[2*i2]   = __floats2half2_rn((v1.x - mean)*rstd*g.x + b.x, (v1.y - mean)*rstd*g.y + b.y);
        out[2*i2+1] = __floats2half2_rn((v1.z - mean)*rstd*g.z + b.z, (v1.w - mean)*rstd*g.w + b.w);
    }
}

// ===================== weight fp32 -> fp16, transposed (2 matrices per launch) =====================
__global__ __launch_bounds__(256) void cvt_t2_kernel(const float* __restrict__ wa, __half* __restrict__ oa,
                                                     const float* __restrict__ wb, __half* __restrict__ ob) {
    const float* w = (blockIdx.z == 0) ? wa : wb;
    __half*      o = (blockIdx.z == 0) ? oa : ob;
    __shared__ float t[32][33];
    int bx = blockIdx.x * 32;   // n0
    int by = blockIdx.y * 32;   // k0
    int tx = threadIdx.x & 31, ty = threadIdx.x >> 5;
    #pragma unroll
    for (int r = 0; r < 32; r += 8)
        t[ty + r][tx] = w[(size_t)(by + ty + r) * HIDDEN + bx + tx];
    __syncthreads();
    #pragma unroll
    for (int r = 0; r < 32; r += 8)
        o[(size_t)(bx + ty + r) * HIDDEN + by + tx] = __float2half_rn(t[tx][ty + r]);
}

// ===================== pipelined mma.sync GEMM =====================
// C[M,N] = A[M,2048] @ BW^T, BW stored [N,2048] k-contiguous.
// BM=128, BN=128, BK=64. 128 threads = 4 warps (2x2), warp tile 64x64.
// 3-stage cp.async ring (96KB) -> 2 CTAs/SM. Prefetch interleaved into ks-loop.
#define BM 128
#define BN 128
#define BK 64
#define NSTG 3
#define NKT  (HIDDEN / BK)             // 32
#define TILE_A   (BM * 128)            // 16384 B
#define TILE_B   (BN * 128)            // 16384 B
#define STG_BYTES (TILE_A + TILE_B)    // 32768
#define GEMM_SMEM (NSTG * STG_BYTES)   // 98304

// load one quarter (q=0..3) of a stage: A 256 chunks + B 256 chunks of 16B
__device__ __forceinline__ void load_quarter(uint32_t as, uint32_t bs,
                                             const __half* __restrict__ Arow,
                                             const __half* __restrict__ Brow,
                                             int kt, int tid, int q) {
    const __half* a = Arow + kt * BK;
    const __half* b = Brow + kt * BK;
    #pragma unroll
    for (int j = 0; j < 2; j++) {
        int c = q * 256 + tid + j * 128;
        int r = c >> 3, k16 = c & 7;
        uint32_t off = (uint32_t)(r * 128 + k16 * 16);
        CP_ASYNC16(as + SWZ(off), (const char*)(a + (size_t)r * HIDDEN) + k16 * 16);
    }
    #pragma unroll
    for (int j = 0; j < 2; j++) {
        int c = q * 256 + tid + j * 128;
        int r = c >> 3, k16 = c & 7;
        uint32_t off = (uint32_t)(r * 128 + k16 * 16);
        CP_ASYNC16(bs + SWZ(off), (const char*)(b + (size_t)r * HIDDEN) + k16 * 16);
    }
}

template<bool QKV>
__global__ __launch_bounds__(128, 2) void gemm_mma(const __half* __restrict__ A,
                                                   const __half* __restrict__ BW,
                                                   void* __restrict__ Cout) {
    extern __shared__ char smem[];
    uint32_t sb = smem_u32(smem);
    int tid = threadIdx.x;
    int wid = tid >> 5, lane = tid & 31;
    int warp_m = (wid >> 1) * 64;      // 0 or 64
    int warp_n = (wid & 1) * 64;       // 0 or 64
    int m0 = blockIdx.y * BM;
    int n0 = blockIdx.x * BN;

    const __half* Arow = A + (size_t)m0 * HIDDEN;
    const __half* Brow;
    if (QKV) Brow = BW + ((size_t)(n0 >> 11) << 22) + (size_t)(n0 & 2047) * HIDDEN;
    else     Brow = BW + (size_t)n0 * HIDDEN;

    float acc[4][8][4];
    #pragma unroll
    for (int mt = 0; mt < 4; mt++)
        #pragma unroll
        for (int nt = 0; nt < 8; nt++)
            #pragma unroll
            for (int z = 0; z < 4; z++) acc[mt][nt][z] = 0.f;

    // prologue: stages 0,1 <- tiles 0,1
    #pragma unroll
    for (int s = 0; s < NSTG - 1; s++) {
        uint32_t base = sb + s * STG_BYTES;
        #pragma unroll
        for (int q = 0; q < 4; q++)
            load_quarter(base, base + TILE_A, Arow, Brow, s, tid, q);
        CP_COMMIT();
    }

    // per-lane ldmatrix indices (fixed across k)
    int a_row  = warp_m + (lane & 15);             // + mt*16
    int a_kg   = (lane >> 4) * 16;                 // 0 or 16 bytes
    // B x4: lanes 0-7 -> (rows n..n+7, k lo), 8-15 -> (same rows, k hi),
    //       16-23 -> (rows n+8.., k lo), 24-31 -> (rows n+8.., k hi)
    int b_row4 = warp_n + (lane & 7) + ((lane >> 4) << 3);   // + ntp*16
    int b_kg4  = ((lane >> 3) & 1) * 16;

    for (int i = 0; i < NKT; i++) {
        int s = i % NSTG;
        CP_WAIT1();
        __syncthreads();

        int ip = i + NSTG - 1;
        int sn = ip % NSTG;
        uint32_t pbase = sb + sn * STG_BYTES;
        bool do_pf = (ip < NKT);

        uint32_t as_base = sb + s * STG_BYTES;
        uint32_t bs_base = as_base + TILE_A;

        #pragma unroll
        for (int ks = 0; ks < 4; ks++) {
            uint32_t a_frag[4][4];
            uint32_t b_frag[8][2];
            #pragma unroll
            for (int mt = 0; mt < 4; mt++) {
                uint32_t off = (uint32_t)((a_row + mt * 16) * 128 + ks * 32 + a_kg);
                LDSM_X4(a_frag[mt][0], a_frag[mt][1], a_frag[mt][2], a_frag[mt][3],
                        as_base + SWZ(off));
            }
            #pragma unroll
            for (int ntp = 0; ntp < 4; ntp++) {
                uint32_t off = (uint32_t)((b_row4 + ntp * 16) * 128 + ks * 32 + b_kg4);
                LDSM_X4(b_frag[2*ntp][0], b_frag[2*ntp][1],
                        b_frag[2*ntp+1][0], b_frag[2*ntp+1][1],
                        bs_base + SWZ(off));
            }
            // interleave 1/4 of the next tile's global->smem traffic
            if (do_pf) load_quarter(pbase, pbase + TILE_A, Arow, Brow, ip, tid, ks);

            #pragma unroll
            for (int mt = 0; mt < 4; mt++)
                #pragma unroll
                for (int nt = 0; nt < 8; nt++)
                    MMA16816(acc[mt][nt],
                             a_frag[mt][0], a_frag[mt][1], a_frag[mt][2], a_frag[mt][3],
                             b_frag[nt][0], b_frag[nt][1]);
        }
        CP_COMMIT();
    }

    // ---- epilogue: regs -> gmem ----
    int r_base = m0 + warp_m + (lane >> 2);
    int c_base = n0 + warp_n + (lane & 3) * 2;
    #pragma unroll
    for (int mt = 0; mt < 4; mt++) {
        #pragma unroll
        for (int nt = 0; nt < 8; nt++) {
            int row0 = r_base + mt * 16;
            int col  = c_base + nt * 8;
            if (QKV) {
                __half* d0 = (__half*)Cout + (size_t)row0 * (3 * HIDDEN) + col;
                __half* d1 = d0 + (size_t)8 * (3 * HIDDEN);
                *(__half2*)d0 = __floats2half2_rn(acc[mt][nt][0], acc[mt][nt][1]);
                *(__half2*)d1 = __floats2half2_rn(acc[mt][nt][2], acc[mt][nt][3]);
            } else {
                float* d0 = (float*)Cout + (size_t)row0 * HIDDEN + col;
                float* d1 = d0 + (size_t)8 * HIDDEN;
                *(float2*)d0 = make_float2(acc[mt][nt][0], acc[mt][nt][1]);
                *(float2*)d1 = make_float2(acc[mt][nt][2], acc[mt][nt][3]);
            }
        }
    }
}

// ===================== per-token RoPE + 32x32 head-attention =====================
__global__ __launch_bounds__(128) void attn_kernel() {
    int t = blockIdx.x;
    int s = t & (SEQ - 1);
    int tid = threadIdx.x;

    __shared__ float qs[32][68], ks[32][68], vs[32][68];
    __shared__ float ss[32][33];
    __shared__ float cosv[32], sinv[32];

    if (tid < 32) {
        float e = (float)(2 * tid) / 64.0f;
        float p = powf(10000.0f, e);
        float ang = (float)s * (1.0f / p);
        sinv[tid] = sinf(ang);
        cosv[tid] = cosf(ang);
    }
    __syncthreads();

    const __half* qg = g_qkv + (size_t)t * (3 * HIDDEN);
    const __half* kg = qg + HIDDEN;
    const __half* vg = qg + 2 * HIDDEN;

    #pragma unroll
    for (int idx = tid; idx < HIDDEN; idx += 128) {
        int h = idx >> 6, d = idx & 63;
        float c = cosv[h], sn = sinv[h];
        int p = (d < 32) ? (2 * d + 1) : (2 * (d - 32));
        float sgn = (d < 32) ? -1.0f : 1.0f;
        float qv = __half2float(qg[idx]);
        float qp = __half2float(qg[h * 64 + p]);
        qs[h][d] = qv * c + sgn * qp * sn;
        float kv = __half2float(kg[idx]);
        float kp = __half2float(kg[h * 64 + p]);
        ks[h][d] = kv * c + sgn * kp * sn;
        vs[h][d] = __half2float(vg[idx]);
    }
    __syncthreads();

    {
        int i  = tid >> 2;
        int j0 = (tid & 3) * 8;
        float acc[8] = {0,0,0,0,0,0,0,0};
        #pragma unroll
        for (int d = 0; d < 64; d += 4) {
            float4 q4 = *(const float4*)&qs[i][d];
            #pragma unroll
            for (int jj = 0; jj < 8; jj++) {
                float4 k4 = *(const float4*)&ks[j0 + jj][d];
                acc[jj] += q4.x * k4.x + q4.y * k4.y + q4.z * k4.z + q4.w * k4.w;
            }
        }
        #pragma unroll
        for (int jj = 0; jj < 8; jj++)
            ss[i][j0 + jj] = acc[jj] * 0.125f;
    }
    __syncthreads();

    if (tid < 32) {
        float mx = -1e30f;
        #pragma unroll
        for (int j = 0; j < 32; j++) mx = fmaxf(mx, ss[tid][j]);
        float sum = 0.f;
        #pragma unroll
        for (int j = 0; j < 32; j++) {
            float e = expf(ss[tid][j] - mx);
            ss[tid][j] = e;
            sum += e;
        }
        float inv = 1.0f / sum;
        #pragma unroll
        for (int j = 0; j < 32; j++) ss[tid][j] *= inv;
    }
    __syncthreads();

    {
        int i  = tid >> 2;
        int d0 = (tid & 3) * 16;
        float acc[16];
        #pragma unroll
        for (int z = 0; z < 16; z++) acc[z] = 0.f;
        #pragma unroll
        for (int j = 0; j < 32; j++) {
            float p = ss[i][j];
            #pragma unroll
            for (int dd = 0; dd < 16; dd += 4) {
                float4 v4 = *(const float4*)&vs[j][d0 + dd];
                acc[dd]     += p * v4.x;
                acc[dd + 1] += p * v4.y;
                acc[dd + 2] += p * v4.z;
                acc[dd + 3] += p * v4.w;
            }
        }
        __half* og = g_attn + (size_t)t * HIDDEN + i * 64 + d0;
        #pragma unroll
        for (int dd = 0; dd < 16; dd += 2)
            *(__half2*)(og + dd) = __floats2half2_rn(acc[dd], acc[dd + 1]);
    }
}

// ===================== launch =====================
extern "C" void kernel_launch(void* const* d_in, const int* in_sizes, int n_in,
                              void* d_out, int out_size) {
    const float* hs    = (const float*)d_in[0];
    const float* w_q   = (const float*)d_in[1];
    const float* w_k   = (const float*)d_in[2];
    const float* w_v   = (const float*)d_in[3];
    const float* w_o   = (const float*)d_in[4];
    const float* gamma = (const float*)d_in[5];
    const float* beta  = (const float*)d_in[6];

    __half *xdev, *wtdev, *qkvdev, *attndev;
    cudaGetSymbolAddress((void**)&xdev, g_x);
    cudaGetSymbolAddress((void**)&wtdev, g_wt);
    cudaGetSymbolAddress((void**)&qkvdev, g_qkv);
    cudaGetSymbolAddress((void**)&attndev, g_attn);

    cudaFuncSetAttribute(gemm_mma<true>,  cudaFuncAttributeMaxDynamicSharedMemorySize, GEMM_SMEM);
    cudaFuncSetAttribute(gemm_mma<false>, cudaFuncAttributeMaxDynamicSharedMemorySize, GEMM_SMEM);

    // 1) LayerNorm -> fp16            (launch 0)
    ln_kernel<<<NTOK, 256>>>(hs, gamma, beta);

    // 2) weights: fp32 -> fp16 transposed, 2 matrices per launch (launches 1,2)
    {
        dim3 grid(HIDDEN / 32, HIDDEN / 32, 2);
        cvt_t2_kernel<<<grid, 256>>>(w_q, wtdev + 0 * (size_t)HIDDEN * HIDDEN,
                                     w_k, wtdev + 1 * (size_t)HIDDEN * HIDDEN);
        cvt_t2_kernel<<<grid, 256>>>(w_v, wtdev + 2 * (size_t)HIDDEN * HIDDEN,
                                     w_o, wtdev + 3 * (size_t)HIDDEN * HIDDEN);
    }

    // 3) QKV GEMM: [32768, 6144] fp16 (launch 3)
    {
        dim3 grid(3 * HIDDEN / BN, NTOK / BM);   // (48, 256)
        gemm_mma<true><<<grid, 128, GEMM_SMEM>>>(xdev, wtdev, qkvdev);
    }

    // 4) RoPE + per-token head attention (launch 4)
    attn_kernel<<<NTOK, 128>>>();

    // 5) Output GEMM: [32768, 2048] fp32 -> d_out (launch 5 — ncu -s 5 lands here)
    {
        dim3 grid(HIDDEN / BN, NTOK / BM);       // (16, 256)
        gemm_mma<false><<<grid, 128, GEMM_SMEM>>>(attndev, wtdev + 3 * (size_t)HIDDEN * HIDDEN, d_out);
    }
}